// round 1
// baseline (speedup 1.0000x reference)
#include <cuda_runtime.h>
#include <math.h>

// Problem constants (fixed by setup_inputs: B=4, N=2048, D_MODEL=512)
#define N_PTS   2048
#define N_WAVES 256     // D_MODEL / 2
#define TJ      256     // j-tile size == blockDim.x

__global__ __launch_bounds__(TJ) void spatial_embedding_kernel(
    const float* __restrict__ coords,          // (B, N, 3)
    const unsigned char* __restrict__ mask,    // (B, N) bool, 1 = padded
    float* __restrict__ out,                   // (B, N, 512)
    int B)
{
    __shared__ float2 sh_ra[TJ];   // (r, amp) per j in tile

    const int row = blockIdx.x;            // b*N + i
    const int b   = row / N_PTS;
    const int i   = row - b * N_PTS;
    const int tid = threadIdx.x;            // wave index m

    const float* cb = coords + (size_t)b * N_PTS * 3;
    const unsigned char* mb = mask + (size_t)b * N_PTS;

    // query point coordinates (broadcast via L1)
    const float xi = cb[i * 3 + 0];
    const float yi = cb[i * 3 + 1];
    const float zi = cb[i * 3 + 2];
    const float vi = (mb[i] == 0) ? 1.0f : 0.0f;   // valid_i

    // wavenumber k_m = 2*pi / lam_m, lam = geomspace(2, 100, 256)
    // computed in double to match numpy's float64 geomspace then f32 cast
    const double t   = (double)tid / (double)(N_WAVES - 1);
    const double lam = 2.0 * pow(50.0, t);
    const float  k   = (float)(6.283185307179586 / lam);

    float re = 0.0f, im = 0.0f;

    for (int j0 = 0; j0 < N_PTS; j0 += TJ) {
        // ---- Phase A: each thread computes (r, amp) for one pair ----
        {
            const int j = j0 + tid;
            const float xj = cb[j * 3 + 0];
            const float yj = cb[j * 3 + 1];
            const float zj = cb[j * 3 + 2];
            const float dx = xi - xj;
            const float dy = yi - yj;
            const float dz = zi - zj;
            float sq = fmaf(dx, dx, fmaf(dy, dy, dz * dz));
            const bool ok = (j != i) && (mb[j] == 0);
            if (!ok) sq = 1.0f;                 // sq_safe: keep r finite
            const float rs  = rsqrtf(sq);       // 1/r  (single MUFU)
            const float r   = sq * rs;          // r
            const float amp = ok ? (0.07957747154594767f * rs) : 0.0f; // 1/(4*pi*r)
            sh_ra[tid] = make_float2(r, amp);
        }
        __syncthreads();

        // ---- Phase B: every thread sweeps the tile for its own wave ----
        #pragma unroll 8
        for (int jj = 0; jj < TJ; ++jj) {
            const float2 ra = sh_ra[jj];        // broadcast LDS.64
            const float ph = k * ra.x;
            float s, c;
            __sincosf(ph, &s, &c);
            re = fmaf(ra.y, c, re);
            im = fmaf(ra.y, s, im);
        }
        __syncthreads();
    }

    // out[b, i, 2m] = re, out[b, i, 2m+1] = im, zeroed if i padded
    float2* orow = (float2*)(out + (size_t)row * (2 * N_WAVES));
    orow[tid] = make_float2(re * vi, im * vi);
}

extern "C" void kernel_launch(void* const* d_in, const int* in_sizes, int n_in,
                              void* d_out, int out_size)
{
    const float* coords        = (const float*)d_in[0];
    const unsigned char* mask  = (const unsigned char*)d_in[1];
    float* out                 = (float*)d_out;

    const int BN = in_sizes[1];        // B * N
    const int B  = BN / N_PTS;

    dim3 grid(BN);
    dim3 block(TJ);
    spatial_embedding_kernel<<<grid, block>>>(coords, mask, out, B);
}

// round 2
// speedup vs baseline: 1.0000x; 1.0000x over previous
#include <cuda_runtime.h>
#include <math.h>

// Problem constants (fixed by setup_inputs: B=4, N=2048, D_MODEL=512)
#define N_PTS   2048
#define N_WAVES 256     // D_MODEL / 2
#define TJ      256     // j-tile size == blockDim.x

__global__ __launch_bounds__(TJ) void spatial_embedding_kernel(
    const float* __restrict__ coords,          // (B, N, 3)
    const unsigned char* __restrict__ mask,    // (B, N) bool, 1 = padded
    float* __restrict__ out,                   // (B, N, 512)
    int B)
{
    __shared__ float2 sh_ra[TJ];   // (r, amp) per j in tile

    const int row = blockIdx.x;            // b*N + i
    const int b   = row / N_PTS;
    const int i   = row - b * N_PTS;
    const int tid = threadIdx.x;            // wave index m

    const float* cb = coords + (size_t)b * N_PTS * 3;
    const unsigned char* mb = mask + (size_t)b * N_PTS;

    // query point coordinates (broadcast via L1)
    const float xi = cb[i * 3 + 0];
    const float yi = cb[i * 3 + 1];
    const float zi = cb[i * 3 + 2];
    const float vi = (mb[i] == 0) ? 1.0f : 0.0f;   // valid_i

    // wavenumber k_m = 2*pi / lam_m, lam = geomspace(2, 100, 256)
    // computed in double to match numpy's float64 geomspace then f32 cast
    const double t   = (double)tid / (double)(N_WAVES - 1);
    const double lam = 2.0 * pow(50.0, t);
    const float  k   = (float)(6.283185307179586 / lam);

    float re = 0.0f, im = 0.0f;

    for (int j0 = 0; j0 < N_PTS; j0 += TJ) {
        // ---- Phase A: each thread computes (r, amp) for one pair ----
        {
            const int j = j0 + tid;
            const float xj = cb[j * 3 + 0];
            const float yj = cb[j * 3 + 1];
            const float zj = cb[j * 3 + 2];
            const float dx = xi - xj;
            const float dy = yi - yj;
            const float dz = zi - zj;
            float sq = fmaf(dx, dx, fmaf(dy, dy, dz * dz));
            const bool ok = (j != i) && (mb[j] == 0);
            if (!ok) sq = 1.0f;                 // sq_safe: keep r finite
            const float rs  = rsqrtf(sq);       // 1/r  (single MUFU)
            const float r   = sq * rs;          // r
            const float amp = ok ? (0.07957747154594767f * rs) : 0.0f; // 1/(4*pi*r)
            sh_ra[tid] = make_float2(r, amp);
        }
        __syncthreads();

        // ---- Phase B: every thread sweeps the tile for its own wave ----
        #pragma unroll 8
        for (int jj = 0; jj < TJ; ++jj) {
            const float2 ra = sh_ra[jj];        // broadcast LDS.64
            const float ph = k * ra.x;
            float s, c;
            __sincosf(ph, &s, &c);
            re = fmaf(ra.y, c, re);
            im = fmaf(ra.y, s, im);
        }
        __syncthreads();
    }

    // out[b, i, 2m] = re, out[b, i, 2m+1] = im, zeroed if i padded
    float2* orow = (float2*)(out + (size_t)row * (2 * N_WAVES));
    orow[tid] = make_float2(re * vi, im * vi);
}

extern "C" void kernel_launch(void* const* d_in, const int* in_sizes, int n_in,
                              void* d_out, int out_size)
{
    const float* coords        = (const float*)d_in[0];
    const unsigned char* mask  = (const unsigned char*)d_in[1];
    float* out                 = (float*)d_out;

    const int BN = in_sizes[1];        // B * N
    const int B  = BN / N_PTS;

    dim3 grid(BN);
    dim3 block(TJ);
    spatial_embedding_kernel<<<grid, block>>>(coords, mask, out, B);
}

// round 3
// speedup vs baseline: 1.7894x; 1.7893x over previous
#include <cuda_runtime.h>
#include <math.h>

// Problem constants (fixed by setup_inputs: B=4, N=2048, D_MODEL=512)
#define N_PTS   2048
#define N_WAVES 256              // D_MODEL / 2
#define T       16               // tile rows
#define NT      (N_PTS / T)      // 128 tiles
#define W       8                // j-tiles per strip
#define NSTRIPS (NT / W)         // 16

__device__ __forceinline__ void red_add_v2(float* p, float x, float y) {
    asm volatile("red.global.add.v2.f32 [%0], {%1, %2};"
                 :: "l"(p), "f"(x), "f"(y) : "memory");
}

__global__ __launch_bounds__(256, 2) void spatial_embedding_sym_kernel(
    const float* __restrict__ coords,          // (B, N, 3)
    const unsigned char* __restrict__ mask,    // (B, N) bool, 1 = padded
    float* __restrict__ out)                   // (B, N, 512), pre-zeroed
{
    __shared__ float4 shp[T * T];              // (r, ampA, ampB, -)
    __shared__ float sxi[T], syi[T], szi[T], svi[T];
    __shared__ float sxj[T], syj[T], szj[T], svj[T];

    const int strip = blockIdx.x;
    const int ti    = blockIdx.y;
    const int b     = blockIdx.z;
    const int tid   = threadIdx.x;             // wave index m

    const int tj_end = strip * W + W;
    if (tj_end <= ti) return;                  // strip entirely below diagonal
    const int tj_beg = (ti > strip * W) ? ti : strip * W;

    const float* cb = coords + (size_t)b * N_PTS * 3;
    const unsigned char* mb = mask + (size_t)b * N_PTS;

    // k_m = 2*pi / lam_m, lam = geomspace(2, 100, 256); double to match numpy
    const double tt = (double)tid / (double)(N_WAVES - 1);
    const float  k  = (float)(6.283185307179586 / (2.0 * pow(50.0, tt)));

    if (tid < T) {
        const int ig = ti * T + tid;
        sxi[tid] = cb[ig * 3 + 0];
        syi[tid] = cb[ig * 3 + 1];
        szi[tid] = cb[ig * 3 + 2];
        svi[tid] = (mb[ig] == 0) ? 1.0f : 0.0f;
    }

    // i-side accumulators persist across the whole strip
    float aiR[T], aiI[T];
    #pragma unroll
    for (int q = 0; q < T; ++q) { aiR[q] = 0.0f; aiI[q] = 0.0f; }

    for (int tj = tj_beg; tj < tj_end; ++tj) {
        __syncthreads();   // covers svi/sxi visibility and shp/j-array reuse
        if (tid < T) {
            const int jg = tj * T + tid;
            sxj[tid] = cb[jg * 3 + 0];
            syj[tid] = cb[jg * 3 + 1];
            szj[tid] = cb[jg * 3 + 2];
            svj[tid] = (mb[jg] == 0) ? 1.0f : 0.0f;
        }
        __syncthreads();

        // ---- Phase A: 256 threads build the 16x16 pair table ----
        {
            const int ii = tid >> 4;
            const int jj = tid & (T - 1);
            const float dx = sxi[ii] - sxj[jj];
            const float dy = syi[ii] - syj[jj];
            const float dz = szi[ii] - szj[jj];
            float sq = fmaf(dx, dx, fmaf(dy, dy, dz * dz));
            const bool self = (ti == tj) && (ii == jj);
            if (self) sq = 1.0f;                      // sq_safe
            const float rs = rsqrtf(sq);
            const float r  = sq * rs;
            const float ar = 0.07957747154594767f * rs;   // 1/(4*pi*r)
            // ampA: contribution to row i (source j must be valid, not self)
            const float ampA = (!self && svj[jj] != 0.0f) ? ar : 0.0f;
            // ampB: contribution to row j (source i valid; only off-diag tiles)
            const float ampB = (ti != tj && svi[ii] != 0.0f) ? ar : 0.0f;
            shp[tid] = make_float4(r, ampA, ampB, 0.0f);
        }
        __syncthreads();

        // ---- Phase B: each thread (wave m) sweeps 256 pairs ----
        float ajR[T], ajI[T];
        #pragma unroll
        for (int q = 0; q < T; ++q) { ajR[q] = 0.0f; ajI[q] = 0.0f; }

        #pragma unroll
        for (int ii = 0; ii < T; ++ii) {
            #pragma unroll
            for (int jj = 0; jj < T; ++jj) {
                const float4 ra = shp[ii * T + jj];   // broadcast LDS.128
                float s, c;
                __sincosf(k * ra.x, &s, &c);
                aiR[ii] = fmaf(ra.y, c, aiR[ii]);
                aiI[ii] = fmaf(ra.y, s, aiI[ii]);
                ajR[jj] = fmaf(ra.z, c, ajR[jj]);
                ajI[jj] = fmaf(ra.z, s, ajI[jj]);
            }
        }

        // flush j-side partials (skip diagonal tile: ampB was 0 there)
        if (tj != ti) {
            #pragma unroll
            for (int jj = 0; jj < T; ++jj) {
                const float v = svj[jj];              // target-row validity
                float* p = out + ((size_t)(b * N_PTS) + tj * T + jj) * (2 * N_WAVES)
                               + 2 * tid;
                red_add_v2(p, ajR[jj] * v, ajI[jj] * v);
            }
        }
    }

    // flush i-side partials once per block
    #pragma unroll
    for (int ii = 0; ii < T; ++ii) {
        const float v = svi[ii];                      // target-row validity
        float* p = out + ((size_t)(b * N_PTS) + ti * T + ii) * (2 * N_WAVES)
                       + 2 * tid;
        red_add_v2(p, aiR[ii] * v, aiI[ii] * v);
    }
}

extern "C" void kernel_launch(void* const* d_in, const int* in_sizes, int n_in,
                              void* d_out, int out_size)
{
    const float* coords       = (const float*)d_in[0];
    const unsigned char* mask = (const unsigned char*)d_in[1];
    float* out                = (float*)d_out;

    const int BN = in_sizes[1];        // B * N
    const int B  = BN / N_PTS;

    // output is accumulated atomically -> must start from zero
    cudaMemsetAsync(d_out, 0, (size_t)out_size * sizeof(float), 0);

    dim3 grid(NSTRIPS, NT, B);
    spatial_embedding_sym_kernel<<<grid, 256>>>(coords, mask, out);
}